// round 2
// baseline (speedup 1.0000x reference)
#include <cuda_runtime.h>

#define T_CTX 4096
#define E_DIM 768
#define H_DIM 64
#define B_SZ  8
#define M_ROWS (B_SZ * T_CTX)   // 32768

// Scratch for projected q, k, v  (8 MB each) — device globals, no allocation.
__device__ float g_q[M_ROWS * H_DIM];
__device__ float g_k[M_ROWS * H_DIM];
__device__ float g_v[M_ROWS * H_DIM];

// ---------------------------------------------------------------------------
// Projection: y = x @ W for W in {Wq, Wk, Wv}, selected by blockIdx.y.
// Block: 256 threads, tile 64 rows x 64 cols (full H), K-chunks of 32.
// Thread (tx,ty) = (tid%16, tid/16) owns a 4x4 register tile.
// ---------------------------------------------------------------------------
__global__ __launch_bounds__(256) void proj_kernel(const float* __restrict__ x,
                                                   const float* __restrict__ Wq,
                                                   const float* __restrict__ Wk,
                                                   const float* __restrict__ Wv) {
    __shared__ float xs[64][33];   // +1 pad: conflict-free column reads
    __shared__ float ws[32][64];

    const int tid = threadIdx.x;
    const int tx = tid & 15;
    const int ty = tid >> 4;
    const int m0 = blockIdx.x * 64;

    const float* W    = (blockIdx.y == 0) ? Wq  : (blockIdx.y == 1) ? Wk  : Wv;
    float*       outp = (blockIdx.y == 0) ? g_q : (blockIdx.y == 1) ? g_k : g_v;

    float acc[4][4];
#pragma unroll
    for (int i = 0; i < 4; i++)
#pragma unroll
        for (int j = 0; j < 4; j++) acc[i][j] = 0.f;

    for (int k0 = 0; k0 < E_DIM; k0 += 32) {
        __syncthreads();
#pragma unroll
        for (int i = 0; i < 8; i++) {           // 64x32 x-tile
            int idx = i * 256 + tid;
            int r = idx >> 5, c = idx & 31;
            xs[r][c] = x[(size_t)(m0 + r) * E_DIM + k0 + c];
        }
#pragma unroll
        for (int i = 0; i < 8; i++) {           // 32x64 W-tile
            int idx = i * 256 + tid;
            int r = idx >> 6, c = idx & 63;
            ws[r][c] = W[(size_t)(k0 + r) * H_DIM + c];
        }
        __syncthreads();
#pragma unroll
        for (int kk = 0; kk < 32; kk++) {
            float a[4];
#pragma unroll
            for (int i = 0; i < 4; i++) a[i] = xs[ty * 4 + i][kk];
            const float4 b4 = *reinterpret_cast<const float4*>(&ws[kk][tx * 4]);
            const float bb[4] = {b4.x, b4.y, b4.z, b4.w};
#pragma unroll
            for (int i = 0; i < 4; i++)
#pragma unroll
                for (int j = 0; j < 4; j++) acc[i][j] += a[i] * bb[j];
        }
    }

#pragma unroll
    for (int i = 0; i < 4; i++) {
        float4 o = make_float4(acc[i][0], acc[i][1], acc[i][2], acc[i][3]);
        *reinterpret_cast<float4*>(
            &outp[(size_t)(m0 + ty * 4 + i) * H_DIM + tx * 4]) = o;
    }
}

// ---------------------------------------------------------------------------
// Causal flash attention (no 1/sqrt(H) scale, faithful to reference).
// Grid: (T/64 q-tiles, B). Block: 256 threads. Online softmax, 4x4 reg tile.
// Shared (dynamic): Qs[64][64], Kst[64][65] (h-major transpose), Vs[64][64],
//                   Ps[64][68].
// ---------------------------------------------------------------------------
#define KP 65
#define PP 68
#define ATT_SMEM_FLOATS (64 * 64 + 64 * KP + 64 * 64 + 64 * PP)
#define ATT_SMEM_BYTES  (ATT_SMEM_FLOATS * 4)

__global__ __launch_bounds__(256) void attn_kernel(float* __restrict__ out) {
    extern __shared__ float sm[];
    float* Qs  = sm;                    // [row][h]   pitch 64
    float* Kst = Qs + 64 * 64;          // [h][kcol]  pitch 65
    float* Vs  = Kst + 64 * KP;         // [krow][h]  pitch 64
    float* Ps  = Vs + 64 * 64;          // [row][kcol] pitch 68

    const int tid = threadIdx.x;
    const int tx = tid & 15;            // 4 cols each
    const int ty = tid >> 4;            // 4 rows each
    const int b  = blockIdx.y;
    const int qt = blockIdx.x;

    const float* qb = g_q + ((size_t)b * T_CTX + (size_t)qt * 64) * H_DIM;
#pragma unroll
    for (int i = 0; i < 16; i++) {
        int idx = i * 256 + tid;
        Qs[idx] = qb[idx];
    }

    float O[4][4];
    float m_i[4], l_i[4];
#pragma unroll
    for (int i = 0; i < 4; i++) {
        m_i[i] = -1e30f;
        l_i[i] = 0.f;
#pragma unroll
        for (int j = 0; j < 4; j++) O[i][j] = 0.f;
    }

    for (int kt = 0; kt <= qt; kt++) {
        __syncthreads();   // previous iteration's consumers of Kst/Vs/Ps done
        const float* kb = g_k + ((size_t)b * T_CTX + (size_t)kt * 64) * H_DIM;
        const float* vb = g_v + ((size_t)b * T_CTX + (size_t)kt * 64) * H_DIM;
#pragma unroll
        for (int i = 0; i < 16; i++) {
            int idx = i * 256 + tid;
            int r = idx >> 6, h = idx & 63;
            Kst[h * KP + r] = kb[idx];   // transpose write, stride 65: no conflicts
            Vs[idx]         = vb[idx];
        }
        __syncthreads();

        // S = Q K^T  (4x4 per thread)
        float S[4][4];
#pragma unroll
        for (int i = 0; i < 4; i++)
#pragma unroll
            for (int j = 0; j < 4; j++) S[i][j] = 0.f;

#pragma unroll 8
        for (int kk = 0; kk < 64; kk++) {
            float a[4], bb[4];
#pragma unroll
            for (int i = 0; i < 4; i++) a[i] = Qs[(ty * 4 + i) * 64 + kk];
#pragma unroll
            for (int j = 0; j < 4; j++) bb[j] = Kst[kk * KP + tx * 4 + j];
#pragma unroll
            for (int i = 0; i < 4; i++)
#pragma unroll
                for (int j = 0; j < 4; j++) S[i][j] += a[i] * bb[j];
        }

        // causal mask on the diagonal tile
        if (kt == qt) {
#pragma unroll
            for (int i = 0; i < 4; i++)
#pragma unroll
                for (int j = 0; j < 4; j++)
                    if (tx * 4 + j > ty * 4 + i) S[i][j] = -1e30f;
        }

        // online softmax (row stats reduced over the 16 tx lanes via shfl)
#pragma unroll
        for (int i = 0; i < 4; i++) {
            float rm = fmaxf(fmaxf(S[i][0], S[i][1]), fmaxf(S[i][2], S[i][3]));
#pragma unroll
            for (int off = 8; off >= 1; off >>= 1)
                rm = fmaxf(rm, __shfl_xor_sync(0xffffffffu, rm, off, 16));
            float mnew  = fmaxf(m_i[i], rm);
            float alpha = __expf(m_i[i] - mnew);
            m_i[i] = mnew;
            float rsum = 0.f;
#pragma unroll
            for (int j = 0; j < 4; j++) {
                float p = __expf(S[i][j] - mnew);
                S[i][j] = p;
                rsum += p;
            }
#pragma unroll
            for (int off = 8; off >= 1; off >>= 1)
                rsum += __shfl_xor_sync(0xffffffffu, rsum, off, 16);
            l_i[i] = l_i[i] * alpha + rsum;
#pragma unroll
            for (int j = 0; j < 4; j++) O[i][j] *= alpha;
        }

        // publish P
#pragma unroll
        for (int i = 0; i < 4; i++)
#pragma unroll
            for (int j = 0; j < 4; j++)
                Ps[(ty * 4 + i) * PP + tx * 4 + j] = S[i][j];
        __syncthreads();

        // O += P V
#pragma unroll 8
        for (int kk = 0; kk < 64; kk++) {
            float p[4];
#pragma unroll
            for (int i = 0; i < 4; i++) p[i] = Ps[(ty * 4 + i) * PP + kk];
            const float4 v4 =
                *reinterpret_cast<const float4*>(&Vs[kk * 64 + tx * 4]);
            const float vv[4] = {v4.x, v4.y, v4.z, v4.w};
#pragma unroll
            for (int i = 0; i < 4; i++)
#pragma unroll
                for (int j = 0; j < 4; j++) O[i][j] += p[i] * vv[j];
        }
    }

    float* ob = out + ((size_t)b * T_CTX + (size_t)qt * 64) * H_DIM;
#pragma unroll
    for (int i = 0; i < 4; i++) {
        float inv = 1.f / l_i[i];
        float4 o = make_float4(O[i][0] * inv, O[i][1] * inv,
                               O[i][2] * inv, O[i][3] * inv);
        *reinterpret_cast<float4*>(&ob[(ty * 4 + i) * H_DIM + tx * 4]) = o;
    }
}

// ---------------------------------------------------------------------------
extern "C" void kernel_launch(void* const* d_in, const int* in_sizes, int n_in,
                              void* d_out, int out_size) {
    const float* x  = (const float*)d_in[0];
    const float* Wq = (const float*)d_in[1];
    const float* Wk = (const float*)d_in[2];
    const float* Wv = (const float*)d_in[3];
    float* out = (float*)d_out;

    cudaFuncSetAttribute(attn_kernel,
                         cudaFuncAttributeMaxDynamicSharedMemorySize,
                         ATT_SMEM_BYTES);

    proj_kernel<<<dim3(M_ROWS / 64, 3), 256>>>(x, Wq, Wk, Wv);
    attn_kernel<<<dim3(T_CTX / 64, B_SZ), 256, ATT_SMEM_BYTES>>>(out);
}